// round 7
// baseline (speedup 1.0000x reference)
#include <cuda_runtime.h>
#include <cuda_bf16.h>

#define NUM_O 1024
#define THREADS 256            // each thread owns 4 output columns: o = tid*4
#define RPT 4                  // rows per tile (whole block per tile)
#define BLOCKS_PER_SM 4
#define GRID_BLOCKS (148 * BLOCKS_PER_SM)

__device__ __forceinline__ float ex2_(float x) {
    float y; asm("ex2.approx.ftz.f32 %0, %1;" : "=f"(y) : "f"(x)); return y;
}

// 4-coeff uniform-sigma fast path (verified R3-R6, rel_err ~2.6e-6):
//   c = exp(-2*ls)*log2e ; sg = -c*|mu|^2 ; s_k = c*(2*mu_k - 1) ; scx = -c
//   arg_true = sg + s0*x0+s1*x1+s2*x2 + scx*(xx-(x0+x1+x2))
// UNI: scx term is per-row constant -> cancels in normalization; remaining
// arg <= 0 for x,mu in [0,1]^3 (no overflow).
template<bool UNI>
__device__ __forceinline__ void run_tiles(
    float4 G, float4 A, float4 B, float4 C, float4 S,
    float (*wsum)[8][RPT], float (*rcp_s)[RPT],
    const float* __restrict__ x, float* __restrict__ out,
    int rows, int tiles, int tid, int warp, int lane)
{
    int parity = 0;

    for (int t = blockIdx.x; t < tiles; t += GRID_BLOCKS, parity ^= 1) {
        const int rbase = t * RPT;

        // x for 4 rows = 12 consecutive floats (rbase*3 = 12t, 16B-aligned).
        float xv[12];
        if (rbase + RPT <= rows) {
            const float4* xp = reinterpret_cast<const float4*>(x + (size_t)rbase * 3);
            float4 u0 = __ldg(xp + 0), u1 = __ldg(xp + 1), u2 = __ldg(xp + 2);
            xv[0]=u0.x; xv[1]=u0.y; xv[2]=u0.z; xv[3]=u0.w;
            xv[4]=u1.x; xv[5]=u1.y; xv[6]=u1.z; xv[7]=u1.w;
            xv[8]=u2.x; xv[9]=u2.y; xv[10]=u2.z; xv[11]=u2.w;
        } else {
            #pragma unroll
            for (int r = 0; r < RPT; r++) {
                int rc = (rbase + r < rows) ? (rbase + r) : (rows - 1);
                xv[r*3+0] = __ldg(&x[rc*3+0]);
                xv[r*3+1] = __ldg(&x[rc*3+1]);
                xv[r*3+2] = __ldg(&x[rc*3+2]);
            }
        }

        float e[RPT][4];
        float acc[RPT];

        #pragma unroll
        for (int r = 0; r < RPT; r++) {
            const float x0 = xv[r*3+0], x1 = xv[r*3+1], x2 = xv[r*3+2];
            float b0 = G.x, b1 = G.y, b2 = G.z, b3 = G.w;
            if (!UNI) {
                float sxm = (x0*x0 + x1*x1 + x2*x2) - (x0 + x1 + x2);
                b0 = fmaf(S.x, sxm, b0); b1 = fmaf(S.y, sxm, b1);
                b2 = fmaf(S.z, sxm, b2); b3 = fmaf(S.w, sxm, b3);
            }
            b0 = fmaf(C.x, x2, b0); b1 = fmaf(C.y, x2, b1);
            b2 = fmaf(C.z, x2, b2); b3 = fmaf(C.w, x2, b3);
            b0 = fmaf(B.x, x1, b0); b1 = fmaf(B.y, x1, b1);
            b2 = fmaf(B.z, x1, b2); b3 = fmaf(B.w, x1, b3);
            b0 = fmaf(A.x, x0, b0); b1 = fmaf(A.y, x0, b1);
            b2 = fmaf(A.z, x0, b2); b3 = fmaf(A.w, x0, b3);

            float v0 = ex2_(b0), v1 = ex2_(b1), v2 = ex2_(b2), v3 = ex2_(b3);
            e[r][0] = v0; e[r][1] = v1; e[r][2] = v2; e[r][3] = v3;
            acc[r] = (v0 + v1) + (v2 + v3);
        }

        // Stage 1: warp-level partial row sums (128 outputs each).
        #pragma unroll
        for (int r = 0; r < RPT; r++) {
            float s = acc[r];
            #pragma unroll
            for (int off = 16; off > 0; off >>= 1)
                s += __shfl_xor_sync(0xFFFFFFFFu, s, off);
            acc[r] = s;
        }
        if (lane < RPT) wsum[parity][warp][lane] = acc[lane];
        __syncthreads();

        // Stage 2: warp 0 reduces across the 8 warps; lane = w*4 + r.
        if (warp == 0) {
            float v = wsum[parity][lane >> 2][lane & 3];
            v += __shfl_xor_sync(0xFFFFFFFFu, v, 16);
            v += __shfl_xor_sync(0xFFFFFFFFu, v, 8);
            v += __shfl_xor_sync(0xFFFFFFFFu, v, 4);
            if (lane < RPT) rcp_s[parity][lane] = 1.0f / v;
        }
        __syncthreads();

        const float4 R4 = *reinterpret_cast<const float4*>(&rcp_s[parity][0]);
        const float rr[RPT] = {R4.x, R4.y, R4.z, R4.w};

        float* orow = out + (size_t)rbase * NUM_O + tid * 4;
        #pragma unroll
        for (int r = 0; r < RPT; r++, orow += NUM_O) {
            if (rbase + r >= rows) break;
            float4 v;
            v.x = e[r][0] * rr[r];
            v.y = e[r][1] * rr[r];
            v.z = e[r][2] * rr[r];
            v.w = e[r][3] * rr[r];
            *reinterpret_cast<float4*>(orow) = v;
        }
    }
}

__global__ void __launch_bounds__(THREADS, BLOCKS_PER_SM)
gaussian_rbf_kernel(const float* __restrict__ x,
                    const float* __restrict__ mus,
                    const float* __restrict__ log_sigmas,
                    float* __restrict__ out,
                    int rows)
{
    __shared__ float wsum[2][8][RPT];
    __shared__ __align__(16) float rcp_s[2][RPT];

    const int tid  = threadIdx.x;
    const int warp = tid >> 5;
    const int lane = tid & 31;

    // --- Per-thread coefficient setup (o = tid*4 .. tid*4+3), all registers ---
    const float LOG2E = 1.4426950408889634f;
    const float ls0 = __ldg(&log_sigmas[0]);

    // mus rows 4t..4t+3 = 12 consecutive floats at index 12*tid (16B-aligned).
    const float4* mp = reinterpret_cast<const float4*>(mus + (size_t)tid * 12);
    float4 M0 = __ldg(mp + 0), M1 = __ldg(mp + 1), M2 = __ldg(mp + 2);
    float4 LS = __ldg(reinterpret_cast<const float4*>(log_sigmas + (size_t)tid * 4));

    bool uni = (LS.x == ls0) & (LS.y == ls0) & (LS.z == ls0) & (LS.w == ls0);
    int uall = __syncthreads_and(uni ? 1 : 0);

    float m0[4] = {M0.x, M0.w, M1.z, M2.y};
    float m1[4] = {M0.y, M1.x, M1.w, M2.z};
    float m2[4] = {M0.z, M1.y, M2.x, M2.w};
    float lsv[4] = {LS.x, LS.y, LS.z, LS.w};

    float4 G, A, B, C, S;
    float* Gp = &G.x; float* Ap = &A.x; float* Bp = &B.x;
    float* Cp = &C.x; float* Sp = &S.x;
    #pragma unroll
    for (int k = 0; k < 4; k++) {
        float c = __expf(-2.0f * lsv[k]) * LOG2E;
        Gp[k] = -c * (m0[k]*m0[k] + m1[k]*m1[k] + m2[k]*m2[k]);
        Ap[k] = c * (2.0f * m0[k] - 1.0f);
        Bp[k] = c * (2.0f * m1[k] - 1.0f);
        Cp[k] = c * (2.0f * m2[k] - 1.0f);
        Sp[k] = -c;
    }

    const int tiles = (rows + RPT - 1) / RPT;

    if (uall)
        run_tiles<true >(G, A, B, C, S, wsum, rcp_s, x, out, rows, tiles, tid, warp, lane);
    else
        run_tiles<false>(G, A, B, C, S, wsum, rcp_s, x, out, rows, tiles, tid, warp, lane);
}

extern "C" void kernel_launch(void* const* d_in, const int* in_sizes, int n_in,
                              void* d_out, int out_size) {
    const float* x          = (const float*)d_in[0];  // (B,S,3)
    const float* mus        = (const float*)d_in[1];  // (1024,3)
    const float* log_sigmas = (const float*)d_in[2];  // (1024,)
    float* out = (float*)d_out;

    const int rows = in_sizes[0] / 3;  // B*S
    gaussian_rbf_kernel<<<GRID_BLOCKS, THREADS>>>(x, mus, log_sigmas, out, rows);
}

// round 8
// speedup vs baseline: 1.0215x; 1.0215x over previous
#include <cuda_runtime.h>
#include <cuda_bf16.h>

#define NUM_O 1024
#define THREADS 256
#define WARPS 8
#define BLOCKS_PER_SM 4
#define GRID_BLOCKS (148 * BLOCKS_PER_SM)
#define TOTAL_WARPS (GRID_BLOCKS * WARPS)

__device__ __forceinline__ float ex2_(float x) {
    float y; asm("ex2.approx.ftz.f32 %0, %1;" : "=f"(y) : "f"(x)); return y;
}

// 4-coeff uniform-sigma fast path (verified R3-R7, rel_err ~2.6e-6):
//   c = exp(-2*ls)*log2e ; sg = -c*|mu|^2 ; s_k = c*(2*mu_k - 1) ; scx = -c
//   arg_true = sg + s0*x0+s1*x1+s2*x2 + scx*(xx-(x0+x1+x2))
// UNI: scx term is per-row constant -> cancels in normalization; remaining
// arg <= 0 for x,mu in [0,1]^3 (no overflow).
template<bool UNI>
__device__ __forceinline__ void run_rows(
    const float* __restrict__ sg, const float* __restrict__ s0,
    const float* __restrict__ s1, const float* __restrict__ s2,
    const float* __restrict__ scx,
    const float* __restrict__ x, float* __restrict__ out,
    int rows, int gwarp, int lane)
{
    // Warp-autonomous: each warp owns one full row per iteration. No barriers.
    for (int row = gwarp; row < rows; row += TOTAL_WARPS) {
        const float x0 = __ldg(&x[row * 3 + 0]);
        const float x1 = __ldg(&x[row * 3 + 1]);
        const float x2 = __ldg(&x[row * 3 + 2]);
        float sxm;
        if (!UNI) sxm = (x0*x0 + x1*x1 + x2*x2) - (x0 + x1 + x2);

        float e[32];
        float acc = 0.0f;

        #pragma unroll
        for (int j = 0; j < 8; j++) {
            const int o = j * 128 + lane * 4;
            const float4 G = *reinterpret_cast<const float4*>(sg + o);
            const float4 A = *reinterpret_cast<const float4*>(s0 + o);
            const float4 B = *reinterpret_cast<const float4*>(s1 + o);
            const float4 C = *reinterpret_cast<const float4*>(s2 + o);

            float b0 = G.x, b1 = G.y, b2 = G.z, b3 = G.w;
            if (!UNI) {
                const float4 S = *reinterpret_cast<const float4*>(scx + o);
                b0 = fmaf(S.x, sxm, b0); b1 = fmaf(S.y, sxm, b1);
                b2 = fmaf(S.z, sxm, b2); b3 = fmaf(S.w, sxm, b3);
            }
            b0 = fmaf(C.x, x2, b0); b1 = fmaf(C.y, x2, b1);
            b2 = fmaf(C.z, x2, b2); b3 = fmaf(C.w, x2, b3);
            b0 = fmaf(B.x, x1, b0); b1 = fmaf(B.y, x1, b1);
            b2 = fmaf(B.z, x1, b2); b3 = fmaf(B.w, x1, b3);
            b0 = fmaf(A.x, x0, b0); b1 = fmaf(A.y, x0, b1);
            b2 = fmaf(A.z, x0, b2); b3 = fmaf(A.w, x0, b3);

            const float v0 = ex2_(b0), v1 = ex2_(b1), v2 = ex2_(b2), v3 = ex2_(b3);
            e[j*4+0] = v0; e[j*4+1] = v1; e[j*4+2] = v2; e[j*4+3] = v3;
            acc += (v0 + v1) + (v2 + v3);
        }

        // Warp-local row sum (all lanes end with the total).
        #pragma unroll
        for (int off = 16; off > 0; off >>= 1)
            acc += __shfl_xor_sync(0xFFFFFFFFu, acc, off);
        const float rcp = 1.0f / acc;

        float* orow = out + (size_t)row * NUM_O + lane * 4;
        #pragma unroll
        for (int j = 0; j < 8; j++) {
            float4 v;
            v.x = e[j*4+0] * rcp;
            v.y = e[j*4+1] * rcp;
            v.z = e[j*4+2] * rcp;
            v.w = e[j*4+3] * rcp;
            *reinterpret_cast<float4*>(orow + j * 128) = v;
        }
    }
}

__global__ void __launch_bounds__(THREADS, BLOCKS_PER_SM)
gaussian_rbf_kernel(const float* __restrict__ x,
                    const float* __restrict__ mus,
                    const float* __restrict__ log_sigmas,
                    float* __restrict__ out,
                    int rows)
{
    __shared__ __align__(16) float sg[NUM_O];
    __shared__ __align__(16) float s0[NUM_O];
    __shared__ __align__(16) float s1[NUM_O];
    __shared__ __align__(16) float s2[NUM_O];
    __shared__ __align__(16) float scx[NUM_O];

    const float LOG2E = 1.4426950408889634f;
    const float ls0 = __ldg(&log_sigmas[0]);
    bool uni = true;

    for (int o = threadIdx.x; o < NUM_O; o += THREADS) {
        float ls = __ldg(&log_sigmas[o]);
        uni = uni && (ls == ls0);
        float m0 = mus[3*o + 0];
        float m1 = mus[3*o + 1];
        float m2 = mus[3*o + 2];
        float c = __expf(-2.0f * ls) * LOG2E;
        sg[o] = -c * (m0*m0 + m1*m1 + m2*m2);
        s0[o] = c * (2.0f * m0 - 1.0f);
        s1[o] = c * (2.0f * m1 - 1.0f);
        s2[o] = c * (2.0f * m2 - 1.0f);
        scx[o] = -c;
    }
    int uall = __syncthreads_and(uni ? 1 : 0);
    // No further block-wide synchronization: warps proceed independently.

    const int warp  = threadIdx.x >> 5;
    const int lane  = threadIdx.x & 31;
    const int gwarp = blockIdx.x * WARPS + warp;

    if (uall)
        run_rows<true >(sg, s0, s1, s2, scx, x, out, rows, gwarp, lane);
    else
        run_rows<false>(sg, s0, s1, s2, scx, x, out, rows, gwarp, lane);
}

extern "C" void kernel_launch(void* const* d_in, const int* in_sizes, int n_in,
                              void* d_out, int out_size) {
    const float* x          = (const float*)d_in[0];  // (B,S,3)
    const float* mus        = (const float*)d_in[1];  // (1024,3)
    const float* log_sigmas = (const float*)d_in[2];  // (1024,)
    float* out = (float*)d_out;

    const int rows = in_sizes[0] / 3;  // B*S
    gaussian_rbf_kernel<<<GRID_BLOCKS, THREADS>>>(x, mus, log_sigmas, out, rows);
}

// round 9
// speedup vs baseline: 1.1646x; 1.1402x over previous
#include <cuda_runtime.h>
#include <cuda_bf16.h>

#define NUM_O 1024
#define THREADS 256
#define WARPS 8
#define BLOCKS_PER_SM 2
#define GRID_BLOCKS (148 * BLOCKS_PER_SM)
#define TOTAL_WARPS (GRID_BLOCKS * WARPS)

__device__ __forceinline__ float ex2_(float x) {
    float y; asm("ex2.approx.ftz.f32 %0, %1;" : "=f"(y) : "f"(x)); return y;
}

// 4-coeff uniform-sigma fast path (verified R3-R8, rel_err ~2.6e-6):
//   c = exp(-2*ls)*log2e ; sg = -c*|mu|^2 ; s_k = c*(2*mu_k - 1) ; scx = -c
//   arg_true = sg + s0*x0+s1*x1+s2*x2 + scx*(xx-(x0+x1+x2))
// UNI: scx term is per-row constant -> cancels in normalization; remaining
// arg <= 0 for x,mu in [0,1]^3 (no overflow).
template<bool UNI>
__device__ __forceinline__ void run_rows2(
    const float* __restrict__ sg, const float* __restrict__ s0,
    const float* __restrict__ s1, const float* __restrict__ s2,
    const float* __restrict__ scx,
    const float* __restrict__ x, float* __restrict__ out,
    int rows, int gwarp, int lane)
{
    // Warp-autonomous: each warp owns TWO rows per iteration. No barriers.
    for (int row = gwarp * 2; row < rows; row += TOTAL_WARPS * 2) {
        const int rowB = (row + 1 < rows) ? (row + 1) : row;

        const float xa0 = __ldg(&x[row  * 3 + 0]);
        const float xa1 = __ldg(&x[row  * 3 + 1]);
        const float xa2 = __ldg(&x[row  * 3 + 2]);
        const float xb0 = __ldg(&x[rowB * 3 + 0]);
        const float xb1 = __ldg(&x[rowB * 3 + 1]);
        const float xb2 = __ldg(&x[rowB * 3 + 2]);
        float sxa, sxb;
        if (!UNI) {
            sxa = (xa0*xa0 + xa1*xa1 + xa2*xa2) - (xa0 + xa1 + xa2);
            sxb = (xb0*xb0 + xb1*xb1 + xb2*xb2) - (xb0 + xb1 + xb2);
        }

        float ea[32], eb[32];
        float accA = 0.0f, accB = 0.0f;

        #pragma unroll
        for (int j = 0; j < 8; j++) {
            const int o = j * 128 + lane * 4;
            const float4 G = *reinterpret_cast<const float4*>(sg + o);
            const float4 A = *reinterpret_cast<const float4*>(s0 + o);
            const float4 B = *reinterpret_cast<const float4*>(s1 + o);
            const float4 C = *reinterpret_cast<const float4*>(s2 + o);

            float a0 = G.x, a1 = G.y, a2 = G.z, a3 = G.w;
            float b0 = G.x, b1 = G.y, b2 = G.z, b3 = G.w;
            if (!UNI) {
                const float4 S = *reinterpret_cast<const float4*>(scx + o);
                a0 = fmaf(S.x, sxa, a0); a1 = fmaf(S.y, sxa, a1);
                a2 = fmaf(S.z, sxa, a2); a3 = fmaf(S.w, sxa, a3);
                b0 = fmaf(S.x, sxb, b0); b1 = fmaf(S.y, sxb, b1);
                b2 = fmaf(S.z, sxb, b2); b3 = fmaf(S.w, sxb, b3);
            }
            a0 = fmaf(C.x, xa2, a0); a1 = fmaf(C.y, xa2, a1);
            a2 = fmaf(C.z, xa2, a2); a3 = fmaf(C.w, xa2, a3);
            b0 = fmaf(C.x, xb2, b0); b1 = fmaf(C.y, xb2, b1);
            b2 = fmaf(C.z, xb2, b2); b3 = fmaf(C.w, xb2, b3);
            a0 = fmaf(B.x, xa1, a0); a1 = fmaf(B.y, xa1, a1);
            a2 = fmaf(B.z, xa1, a2); a3 = fmaf(B.w, xa1, a3);
            b0 = fmaf(B.x, xb1, b0); b1 = fmaf(B.y, xb1, b1);
            b2 = fmaf(B.z, xb1, b2); b3 = fmaf(B.w, xb1, b3);
            a0 = fmaf(A.x, xa0, a0); a1 = fmaf(A.y, xa0, a1);
            a2 = fmaf(A.z, xa0, a2); a3 = fmaf(A.w, xa0, a3);
            b0 = fmaf(A.x, xb0, b0); b1 = fmaf(A.y, xb0, b1);
            b2 = fmaf(A.z, xb0, b2); b3 = fmaf(A.w, xb0, b3);

            const float va0 = ex2_(a0), va1 = ex2_(a1), va2 = ex2_(a2), va3 = ex2_(a3);
            const float vb0 = ex2_(b0), vb1 = ex2_(b1), vb2 = ex2_(b2), vb3 = ex2_(b3);
            ea[j*4+0] = va0; ea[j*4+1] = va1; ea[j*4+2] = va2; ea[j*4+3] = va3;
            eb[j*4+0] = vb0; eb[j*4+1] = vb1; eb[j*4+2] = vb2; eb[j*4+3] = vb3;
            accA += (va0 + va1) + (va2 + va3);
            accB += (vb0 + vb1) + (vb2 + vb3);
        }

        // Warp-local row sums.
        #pragma unroll
        for (int off = 16; off > 0; off >>= 1) {
            accA += __shfl_xor_sync(0xFFFFFFFFu, accA, off);
            accB += __shfl_xor_sync(0xFFFFFFFFu, accB, off);
        }
        const float rcpA = 1.0f / accA;
        const float rcpB = 1.0f / accB;

        float* orowA = out + (size_t)row * NUM_O + lane * 4;
        #pragma unroll
        for (int j = 0; j < 8; j++) {
            float4 v;
            v.x = ea[j*4+0] * rcpA; v.y = ea[j*4+1] * rcpA;
            v.z = ea[j*4+2] * rcpA; v.w = ea[j*4+3] * rcpA;
            *reinterpret_cast<float4*>(orowA + j * 128) = v;
        }
        if (rowB != row) {
            float* orowB = out + (size_t)rowB * NUM_O + lane * 4;
            #pragma unroll
            for (int j = 0; j < 8; j++) {
                float4 v;
                v.x = eb[j*4+0] * rcpB; v.y = eb[j*4+1] * rcpB;
                v.z = eb[j*4+2] * rcpB; v.w = eb[j*4+3] * rcpB;
                *reinterpret_cast<float4*>(orowB + j * 128) = v;
            }
        }
    }
}

__global__ void __launch_bounds__(THREADS, BLOCKS_PER_SM)
gaussian_rbf_kernel(const float* __restrict__ x,
                    const float* __restrict__ mus,
                    const float* __restrict__ log_sigmas,
                    float* __restrict__ out,
                    int rows)
{
    __shared__ __align__(16) float sg[NUM_O];
    __shared__ __align__(16) float s0[NUM_O];
    __shared__ __align__(16) float s1[NUM_O];
    __shared__ __align__(16) float s2[NUM_O];
    __shared__ __align__(16) float scx[NUM_O];

    const float LOG2E = 1.4426950408889634f;
    const float ls0 = __ldg(&log_sigmas[0]);
    bool uni = true;

    for (int o = threadIdx.x; o < NUM_O; o += THREADS) {
        float ls = __ldg(&log_sigmas[o]);
        uni = uni && (ls == ls0);
        float m0 = mus[3*o + 0];
        float m1 = mus[3*o + 1];
        float m2 = mus[3*o + 2];
        float c = __expf(-2.0f * ls) * LOG2E;
        sg[o] = -c * (m0*m0 + m1*m1 + m2*m2);
        s0[o] = c * (2.0f * m0 - 1.0f);
        s1[o] = c * (2.0f * m1 - 1.0f);
        s2[o] = c * (2.0f * m2 - 1.0f);
        scx[o] = -c;
    }
    int uall = __syncthreads_and(uni ? 1 : 0);
    // No further block-wide synchronization: warps proceed independently.

    const int warp  = threadIdx.x >> 5;
    const int lane  = threadIdx.x & 31;
    const int gwarp = blockIdx.x * WARPS + warp;

    if (uall)
        run_rows2<true >(sg, s0, s1, s2, scx, x, out, rows, gwarp, lane);
    else
        run_rows2<false>(sg, s0, s1, s2, scx, x, out, rows, gwarp, lane);
}

extern "C" void kernel_launch(void* const* d_in, const int* in_sizes, int n_in,
                              void* d_out, int out_size) {
    const float* x          = (const float*)d_in[0];  // (B,S,3)
    const float* mus        = (const float*)d_in[1];  // (1024,3)
    const float* log_sigmas = (const float*)d_in[2];  // (1024,)
    float* out = (float*)d_out;

    const int rows = in_sizes[0] / 3;  // B*S
    gaussian_rbf_kernel<<<GRID_BLOCKS, THREADS>>>(x, mus, log_sigmas, out, rows);
}